// round 11
// baseline (speedup 1.0000x reference)
#include <cuda_runtime.h>

// ---------------- problem constants ----------------
#define Bv 1024
#define Nv 512
#define MI 512
#define ME 16
#define NEWTON_ITERS 8
#define ADMM_IT 15
#define ALPHA_C 0.05f

enum { EPI_NONE=0, EPI_ADD_I, EPI_NEWTON, EPI_SUB_FROM_D,
       EPI_ADD_ROW, EPI_ADD_D_ROW, EPI_INIT_WU, EPI_ADMM, EPI_FINAL_PGD };

// ---------------- scratch layout ----------------
constexpr size_t SZ_MAT  = 512*512;
constexpr size_t SZ_BAT  = (size_t)Bv*512;
constexpr size_t OFF_M   = 0;
constexpr size_t OFF_XA  = OFF_M  + SZ_MAT;
constexpr size_t OFF_XB  = OFF_XA + SZ_MAT;
constexpr size_t OFF_T   = OFF_XB + SZ_MAT;
constexpr size_t OFF_P   = OFF_T  + SZ_MAT;
constexpr size_t OFF_GP  = OFF_P  + SZ_MAT;
constexpr size_t OFF_V   = OFF_GP + SZ_MAT;
constexpr size_t OFF_AMI = OFF_V  + SZ_MAT;          // 16*512
constexpr size_t OFF_S   = OFF_AMI + (size_t)ME*Nv;  // 16*16
constexpr size_t OFF_SI  = OFF_S  + (size_t)ME*ME;
constexpr size_t OFF_W   = OFF_SI + (size_t)ME*ME;   // 512*16
constexpr size_t OFF_Q0  = OFF_W  + (size_t)Nv*ME;
constexpr size_t OFF_G0  = OFF_Q0 + Nv;
constexpr size_t OFF_CV  = OFF_G0 + MI;
constexpr size_t OFF_X   = OFF_CV + 64;
constexpr size_t OFF_Y   = OFF_X  + SZ_BAT;
constexpr size_t OFF_D   = OFF_Y  + SZ_BAT;
constexpr size_t OFF_XP  = OFF_D  + SZ_BAT;
constexpr size_t OFF_WB  = OFF_XP + SZ_BAT;
constexpr size_t OFF_W2  = OFF_WB + SZ_BAT;
constexpr size_t OFF_UB  = OFF_W2 + SZ_BAT;
constexpr size_t SCRATCH_FLOATS = OFF_UB + SZ_BAT;

// 256B alignment keeps every float4 / LDG.128 path 16B-aligned (err715 otherwise).
__device__ __align__(256) float g_scratch[SCRATCH_FLOATS];

// ---------------- packed f32x2 helpers (FFMA2 path, PTX-only) ----------------
__device__ __forceinline__ void unpack2(unsigned long long v, float &x, float &y) {
    asm("mov.b64 {%0, %1}, %2;" : "=f"(x), "=f"(y) : "l"(v));
}
__device__ __forceinline__ void fma2(unsigned long long &d, unsigned long long a,
                                     unsigned long long b) {
    asm("fma.rn.f32x2 %0, %1, %2, %0;" : "+l"(d) : "l"(a), "l"(b));
}

// ---------------- FFMA2 tiled GEMM, 32x64 tile, duplicated-A smem ----------------
// C (M x N) = opA(A) @ opB(B) with fused epilogue.
// TA=1: A stored (K x M); TB=1: B stored (N x K). 256 threads, thread grid 16x16.
// Thread tile 2(m) x 4(n): acc = 2 m-rows x 2 n-pairs of f32x2.
// As stores every A value DUPLICATED ({a,a} pairs) so the FFMA2 scalar operand
// is a direct LDS.128 (no pack MOVs). Double-buffered BK=16 + register pipeline.
template<int TA, int TB>
__global__ __launch_bounds__(256)
void gemm_k(int M, int N, int K,
            const float* __restrict__ A, int lda,
            const float* __restrict__ B, int ldb,
            float* __restrict__ C, int ldc,
            const float* __restrict__ D,
            const float* __restrict__ row,
            float* __restrict__ C2,
            const float* __restrict__ C3,
            int epi)
{
    __shared__ __align__(16) float As[2][16][64];   // duplicated: [kk][2i{,+1}] = A[i][kk]
    __shared__ __align__(16) float Bs[2][16][64];

    const int tid = threadIdx.x;
    const int tx = tid & 15, ty = tid >> 4;
    const int i0 = blockIdx.y * 32;
    const int j0 = blockIdx.x * 64;

    // ---- loader index precompute ----
    const bool a_act = tid < 128;
    int a_r0, a_r1;
    if (TA == 0) { a_r0 = tid >> 2; a_r1 = tid & 3; }   // row i (0..31), k-quad
    else         { a_r0 = tid >> 3; a_r1 = tid & 7; }   // k row (0..15), m-quad
    int b_r0, b_r1;
    if (TB == 0) { b_r0 = tid >> 4; b_r1 = tid & 15; }  // k row, n-quad
    else         { b_r0 = tid >> 2; b_r1 = tid & 3; }   // n row (0..63), k-quad

    float4 pa = make_float4(0.f, 0.f, 0.f, 0.f);
    float4 pb = make_float4(0.f, 0.f, 0.f, 0.f);

    auto loadA = [&](int k0) {
        if (!a_act) return;
        if (TA == 0) {
            int gi = i0 + a_r0;
            pa = (gi < M) ? *reinterpret_cast<const float4*>(&A[(size_t)gi * lda + k0 + a_r1 * 4])
                          : make_float4(0.f, 0.f, 0.f, 0.f);
        } else {
            int gm = i0 + a_r1 * 4;
            pa = (gm < M) ? *reinterpret_cast<const float4*>(&A[(size_t)(k0 + a_r0) * lda + gm])
                          : make_float4(0.f, 0.f, 0.f, 0.f);
        }
    };
    auto storeA = [&](int buf) {
        if (!a_act) return;
        if (TA == 0) {
            // duplicated {v,v} per k
            *reinterpret_cast<float2*>(&As[buf][a_r1 * 4 + 0][2 * a_r0]) = make_float2(pa.x, pa.x);
            *reinterpret_cast<float2*>(&As[buf][a_r1 * 4 + 1][2 * a_r0]) = make_float2(pa.y, pa.y);
            *reinterpret_cast<float2*>(&As[buf][a_r1 * 4 + 2][2 * a_r0]) = make_float2(pa.z, pa.z);
            *reinterpret_cast<float2*>(&As[buf][a_r1 * 4 + 3][2 * a_r0]) = make_float2(pa.w, pa.w);
        } else {
            // 4 consecutive m -> 8 duplicated floats
            *reinterpret_cast<float4*>(&As[buf][a_r0][8 * a_r1 + 0]) = make_float4(pa.x, pa.x, pa.y, pa.y);
            *reinterpret_cast<float4*>(&As[buf][a_r0][8 * a_r1 + 4]) = make_float4(pa.z, pa.z, pa.w, pa.w);
        }
    };
    auto loadB = [&](int k0) {
        if (TB == 0) {
            int gj = j0 + b_r1 * 4;
            pb = (gj < N) ? *reinterpret_cast<const float4*>(&B[(size_t)(k0 + b_r0) * ldb + gj])
                          : make_float4(0.f, 0.f, 0.f, 0.f);
        } else {
            int gn = j0 + b_r0;
            pb = (gn < N) ? *reinterpret_cast<const float4*>(&B[(size_t)gn * ldb + k0 + b_r1 * 4])
                          : make_float4(0.f, 0.f, 0.f, 0.f);
        }
    };
    auto storeB = [&](int buf) {
        if (TB == 0) {
            *reinterpret_cast<float4*>(&Bs[buf][b_r0][b_r1 * 4]) = pb;
        } else {
            Bs[buf][b_r1 * 4 + 0][b_r0] = pb.x;
            Bs[buf][b_r1 * 4 + 1][b_r0] = pb.y;
            Bs[buf][b_r1 * 4 + 2][b_r0] = pb.z;
            Bs[buf][b_r1 * 4 + 3][b_r0] = pb.w;
        }
    };

    unsigned long long acc00 = 0ULL, acc01 = 0ULL, acc10 = 0ULL, acc11 = 0ULL;

    loadA(0); loadB(0);
    storeA(0); storeB(0);
    __syncthreads();

    const int nk = K >> 4;
    int buf = 0;
    for (int t = 0; t < nk; t++) {
        if (t + 1 < nk) { loadA((t + 1) * 16); loadB((t + 1) * 16); }
        // register-pipelined fragments: af = {{a0,a0},{a1,a1}}, bf = {{b0,b1},{b2,b3}}
        ulonglong2 af = *reinterpret_cast<const ulonglong2*>(&As[buf][0][ty * 4]);
        ulonglong2 bf = *reinterpret_cast<const ulonglong2*>(&Bs[buf][0][tx * 4]);
#pragma unroll
        for (int kk = 0; kk < 16; kk++) {
            ulonglong2 af_n, bf_n;
            if (kk < 15) {
                af_n = *reinterpret_cast<const ulonglong2*>(&As[buf][kk + 1][ty * 4]);
                bf_n = *reinterpret_cast<const ulonglong2*>(&Bs[buf][kk + 1][tx * 4]);
            }
            fma2(acc00, af.x, bf.x);
            fma2(acc01, af.x, bf.y);
            fma2(acc10, af.y, bf.x);
            fma2(acc11, af.y, bf.y);
            if (kk < 15) { af = af_n; bf = bf_n; }
        }
        if (t + 1 < nk) { storeA(buf ^ 1); storeB(buf ^ 1); __syncthreads(); buf ^= 1; }
    }

    // ---- fused epilogue ----
    unsigned long long accs[2][2] = {{acc00, acc01}, {acc10, acc11}};
#pragma unroll
    for (int m = 0; m < 2; m++) {
        int gi = i0 + ty * 2 + m;
        if (gi >= M) continue;
#pragma unroll
        for (int p = 0; p < 2; p++) {
            float v0, v1;
            unpack2(accs[m][p], v0, v1);
#pragma unroll
            for (int e = 0; e < 2; e++) {
                int jj = j0 + tx * 4 + p * 2 + e;
                if (jj >= N) continue;
                float v = e ? v1 : v0;
                size_t o = (size_t)gi * ldc + jj;
                switch (epi) {
                    case EPI_ADD_I:      C[o] = v + ((gi == jj) ? 1.f : 0.f); break;
                    case EPI_NEWTON:     C[o] = 2.f * D[o] - v;               break;
                    case EPI_SUB_FROM_D: C[o] = D[o] - v;                     break;
                    case EPI_ADD_ROW:    C[o] = v + row[jj];                  break;
                    case EPI_ADD_D_ROW:  C[o] = D[o] + v + row[jj];           break;
                    case EPI_INIT_WU:    C[o] = fminf(row[jj], v); C2[o] = 0.f; break;
                    case EPI_ADMM: {
                        float tt = row[jj] - (v + D[o]) - C2[o];
                        C2[o] = fmaxf(-tt, 0.f);
                        C[o]  = row[jj] - fabsf(tt);
                    } break;
                    case EPI_FINAL_PGD: {
                        float z = D[o] + v + row[jj];
                        C[o] = z - ALPHA_C * (z - C3[o]);
                    } break;
                    default:             C[o] = v;                            break;
                }
            }
        }
    }
}

// ---------------- small helper kernels ----------------
__global__ void rowmax_kernel(const float* __restrict__ Mm, float* __restrict__ cval) {
    __shared__ float red[512];
    int i = threadIdx.x;
    float s = 0.f;
    for (int j = 0; j < 512; j++) s += fabsf(Mm[(size_t)i * 512 + j]);
    red[i] = s;
    __syncthreads();
    for (int st = 256; st > 0; st >>= 1) {
        if (i < st) red[i] = fmaxf(red[i], red[i + st]);
        __syncthreads();
    }
    if (i == 0) *cval = 2.0f / (1.0f + red[0]);
}

__global__ void initX_kernel(float* __restrict__ X, const float* __restrict__ cval) {
    int idx = blockIdx.x * blockDim.x + threadIdx.x;
    if (idx < 512 * 512) {
        int i = idx >> 9, j = idx & 511;
        X[idx] = (i == j) ? *cval : 0.f;
    }
}

__global__ void sinv_kernel(const float* __restrict__ S, float* __restrict__ Si) {
    __shared__ float a[16][32];
    int t = threadIdx.x;
    for (int l = 0; l < 2; l++) {
        int idx = t + l * 256;
        int r = idx >> 5, c = idx & 31;
        a[r][c] = (c < 16) ? S[r * 16 + c] : ((c - 16 == r) ? 1.f : 0.f);
    }
    __syncthreads();
    for (int p = 0; p < 16; p++) {
        float pivinv = 1.0f / a[p][p];
        float oldv[2], oldpc[2], oldrp[2];
        int rr[2], cc[2];
        for (int l = 0; l < 2; l++) {
            int idx = t + l * 256;
            int r = idx >> 5, c = idx & 31;
            rr[l] = r; cc[l] = c;
            oldv[l]  = a[r][c];
            oldpc[l] = a[p][c];
            oldrp[l] = a[r][p];
        }
        __syncthreads();
        for (int l = 0; l < 2; l++) {
            int r = rr[l], c = cc[l];
            a[r][c] = (r == p) ? oldv[l] * pivinv
                               : oldv[l] - oldrp[l] * pivinv * oldpc[l];
        }
        __syncthreads();
    }
    for (int l = 0; l < 2; l++) {
        int idx = t + l * 256;
        int r = idx >> 5, c = idx & 31;
        if (c >= 16) Si[r * 16 + (c - 16)] = a[r][c];
    }
}

__global__ void q0_kernel(const float* __restrict__ W, const float* __restrict__ b,
                          float* __restrict__ q0) {
    int i = threadIdx.x;
    if (i < 512) {
        float s = 0.f;
        for (int j = 0; j < 16; j++) s += W[i * 16 + j] * b[j];
        q0[i] = s;
    }
}

__global__ void g0_kernel(const float* __restrict__ G, const float* __restrict__ q0,
                          float* __restrict__ g0) {
    int i = blockIdx.x * blockDim.x + threadIdx.x;
    if (i < MI) {
        float s = 0.f;
        for (int j = 0; j < Nv; j++) s += G[(size_t)i * Nv + j] * q0[j];
        g0[i] = s;
    }
}

// ---------------- host-side dispatch ----------------
static void gemm(int ta, int tb, int M, int N, int K,
                 const float* A, int lda, const float* B, int ldb,
                 float* C, int ldc,
                 const float* D, const float* row, float* C2, const float* C3, int epi)
{
    dim3 blk(256);
    dim3 grid((N + 63) / 64, (M + 31) / 32);
    if (ta)      gemm_k<1,0><<<grid, blk>>>(M,N,K,A,lda,B,ldb,C,ldc,D,row,C2,C3,epi);
    else if (tb) gemm_k<0,1><<<grid, blk>>>(M,N,K,A,lda,B,ldb,C,ldc,D,row,C2,C3,epi);
    else         gemm_k<0,0><<<grid, blk>>>(M,N,K,A,lda,B,ldb,C,ldc,D,row,C2,C3,epi);
}

extern "C" void kernel_launch(void* const* d_in, const int* in_sizes, int n_in,
                              void* d_out, int out_size)
{
    (void)in_sizes; (void)n_in; (void)out_size;
    const float* c = (const float*)d_in[0];   // [B, N]
    const float* G = (const float*)d_in[1];   // [MI, N]
    const float* h = (const float*)d_in[2];   // [MI]
    const float* Am= (const float*)d_in[3];   // [ME, N]
    const float* b = (const float*)d_in[4];   // [ME]
    float* out = (float*)d_out;               // [B, N]

    float* S;
    cudaGetSymbolAddress((void**)&S, g_scratch);
    float* Mm  = S + OFF_M;
    float* Xa  = S + OFF_XA;
    float* Xb  = S + OFF_XB;
    float* Tt  = S + OFF_T;
    float* P   = S + OFF_P;
    float* GP  = S + OFF_GP;
    float* V   = S + OFF_V;
    float* AMi = S + OFF_AMI;
    float* Ss  = S + OFF_S;
    float* Si  = S + OFF_SI;
    float* W   = S + OFF_W;
    float* q0  = S + OFF_Q0;
    float* g0  = S + OFF_G0;
    float* cv  = S + OFF_CV;
    float* xb  = S + OFF_X;
    float* yb  = S + OFF_Y;
    float* db  = S + OFF_D;
    float* xPb = S + OFF_XP;
    float* wb  = S + OFF_WB;
    float* w2  = S + OFF_W2;
    float* ub  = S + OFF_UB;

    // ===== Precompute =====
    // 1) M = G^T G + I
    gemm(1,0, Nv, Nv, MI, G, Nv, G, Nv, Mm, Nv, nullptr, nullptr, nullptr, nullptr, EPI_ADD_I);
    // 2) X0 = (2/(1+||M||_inf)) * I  (lambda_min(M)=1 -> e0=(r-1)/(r+1); 8 iters: e0^256 ~ 1e-11)
    rowmax_kernel<<<1, 512>>>(Mm, cv);
    initX_kernel<<<(512 * 512 + 255) / 256, 256>>>(Xa, cv);
    // 3) Newton-Schulz: X <- 2X - X M X
    float* cur = Xa; float* nxt = Xb;
    for (int it = 0; it < NEWTON_ITERS; it++) {
        gemm(0,0, Nv, Nv, Nv, Mm, Nv, cur, Nv, Tt, Nv, nullptr, nullptr, nullptr, nullptr, EPI_NONE);
        gemm(0,0, Nv, Nv, Nv, cur, Nv, Tt, Nv, nxt, Nv, cur, nullptr, nullptr, nullptr, EPI_NEWTON);
        float* tmp = cur; cur = nxt; nxt = tmp;
    }
    float* Minv = cur;
    // 4-8) Schur pieces
    gemm(0,0, ME, Nv, Nv, Am, Nv, Minv, Nv, AMi, Nv, nullptr, nullptr, nullptr, nullptr, EPI_NONE);
    gemm(0,1, ME, ME, Nv, AMi, Nv, Am, Nv, Ss, ME, nullptr, nullptr, nullptr, nullptr, EPI_NONE);
    sinv_kernel<<<1, 256>>>(Ss, Si);
    gemm(1,0, Nv, ME, ME, AMi, Nv, Si, ME, W, ME, nullptr, nullptr, nullptr, nullptr, EPI_NONE);
    gemm(0,0, Nv, Nv, ME, W, ME, AMi, Nv, P, Nv, Minv, nullptr, nullptr, nullptr, EPI_SUB_FROM_D);
    // 9-10) GP = G@P ; V = GP@G^T
    gemm(0,0, MI, Nv, Nv, G, Nv, P, Nv, GP, Nv, nullptr, nullptr, nullptr, nullptr, EPI_NONE);
    gemm(0,1, MI, MI, Nv, GP, Nv, G, Nv, V, MI, nullptr, nullptr, nullptr, nullptr, EPI_NONE);
    // 11) q0 = W@b ; g0 = G@q0
    q0_kernel<<<1, 512>>>(W, b, q0);
    g0_kernel<<<2, 256>>>(G, q0, g0);

    // ===== Projection with fused ADMM epilogue =====
    auto project = [&](const float* xin, float* zout, int last_epi) {
        // w = min(h, x G^T), u = 0
        gemm(0,1, Bv, MI, Nv, xin, Nv, G,  Nv, wb,  MI, nullptr, h,  ub,      nullptr, EPI_INIT_WU);
        // d = x GP^T + g0
        gemm(0,1, Bv, MI, Nv, xin, Nv, GP, Nv, db,  MI, nullptr, g0, nullptr, nullptr, EPI_ADD_ROW);
        // xP = x P
        gemm(0,0, Bv, Nv, Nv, xin, Nv, P,  Nv, xPb, Nv, nullptr, nullptr, nullptr, nullptr, EPI_NONE);
        // ADMM: Gz = w@V + d; t = h-Gz-u; u' = relu(-t); w' = h-|t|  (w ping-pong, u in-place)
        float* wcur = wb; float* wnext = w2;
        for (int it = 0; it < ADMM_IT; it++) {
            gemm(0,0, Bv, MI, MI, wcur, MI, V, MI, wnext, MI, db, h, ub, nullptr, EPI_ADMM);
            float* tmp = wcur; wcur = wnext; wnext = tmp;
        }
        // z = xP + w@GP + q0  (+ fused PGD toward c when last_epi==EPI_FINAL_PGD)
        gemm(0,0, Bv, Nv, MI, wcur, MI, GP, Nv, zout, Nv, xPb, q0, nullptr, c, last_epi);
    };

    // ===== PGD (pgd step fused into preceding projection's epilogue) =====
    project(c,  yb,  EPI_FINAL_PGD);   // x1 = proj(c); y1 = x1 - a(x1-c)
    project(yb, xb,  EPI_FINAL_PGD);   // x2 = proj(y1); y2 = ...
    project(xb, yb,  EPI_FINAL_PGD);   // x3 = proj(y2); y3 = ...
    project(yb, out, EPI_ADD_D_ROW);   // x4 = proj(y3) -> out
}